// round 5
// baseline (speedup 1.0000x reference)
#include <cuda_runtime.h>
#include <math.h>

// Shapes (compile-time constants for this problem instance)
#define BATCH 4
#define CIN   256
#define GC    64
#define PL    64
#define HL    128
#define WL    128
#define HH    256
#define WW    256
#define PLOW  (HL*WL)        // 16384
#define PFUL  (HH*WW)        // 65536
#define WROW  (CIN+GC)       // 320

// Scratch (device globals — no allocations allowed)
__device__ float  g_ylow[BATCH*PL*PLOW];   // 16 MB: conv1x1 of x at low res
__device__ float  g_xv[BATCH*PL*PFUL];     // 64 MB: v = upsample(ylow) + Wg*guide
__device__ double g_sum[PL];
__device__ double g_sumsq[PL];
__device__ float  g_scale[PL];
__device__ float  g_shift[PL];

// ---- packed fp32x2 helpers (sm_100+ dual-lane fp32; full fp32 precision) ----
__device__ __forceinline__ unsigned long long pk2(float lo, float hi) {
    unsigned long long r;
    asm("mov.b64 %0, {%1, %2};" : "=l"(r) : "f"(lo), "f"(hi));
    return r;
}
__device__ __forceinline__ void upk2(float& lo, float& hi, unsigned long long v) {
    asm("mov.b64 {%0, %1}, %2;" : "=f"(lo), "=f"(hi) : "l"(v));
}
__device__ __forceinline__ void fma2(unsigned long long& d,
                                     unsigned long long a, unsigned long long b) {
    asm("fma.rn.f32x2 %0, %1, %2, %0;" : "+l"(d) : "l"(a), "l"(b));
}

// ---------------------------------------------------------------------------
// K1: y_low[b,o,p] = sum_{c<256} W[o,c] * x[b,c,p]    (GEMM M=64,K=256,N=65536)
// One thread = one low-res pixel. Output channels packed in pairs into f32x2
// accumulators; weights pre-paired in dynamic smem (64 KB).
// ---------------------------------------------------------------------------
__global__ void __launch_bounds__(128) k_conv_low(const float* __restrict__ x,
                                                  const float* __restrict__ Wc) {
    extern __shared__ unsigned long long sW2[];   // [CIN][32] packed pairs (16B-aligned base)
    int tid = threadIdx.x;
    for (int i = tid; i < CIN*32; i += 128) {
        int c  = i >> 5;        // 0..255
        int o2 = i & 31;        // pair index
        sW2[i] = pk2(Wc[(2*o2)*WROW + c], Wc[(2*o2+1)*WROW + c]);
    }
    __syncthreads();

    int gp = blockIdx.x * 128 + tid;      // 0 .. BATCH*PLOW-1
    int b  = gp >> 14;                    // /16384
    int p  = gp & (PLOW-1);
    const float* xb = x + b*CIN*PLOW + p;

    unsigned long long acc2[32];
#pragma unroll
    for (int o = 0; o < 32; o++) acc2[o] = 0ULL;

    for (int c = 0; c < CIN; c += 4) {
        unsigned long long vv0 = pk2(xb[(c+0)*PLOW], xb[(c+0)*PLOW]);
        unsigned long long vv1 = pk2(xb[(c+1)*PLOW], xb[(c+1)*PLOW]);
        unsigned long long vv2 = pk2(xb[(c+2)*PLOW], xb[(c+2)*PLOW]);
        unsigned long long vv3 = pk2(xb[(c+3)*PLOW], xb[(c+3)*PLOW]);
#pragma unroll
        for (int o2 = 0; o2 < 32; o2 += 2) {
            ulonglong2 w0 = *(const ulonglong2*)&sW2[(c+0)*32 + o2];
            fma2(acc2[o2],   w0.x, vv0);  fma2(acc2[o2+1], w0.y, vv0);
            ulonglong2 w1 = *(const ulonglong2*)&sW2[(c+1)*32 + o2];
            fma2(acc2[o2],   w1.x, vv1);  fma2(acc2[o2+1], w1.y, vv1);
            ulonglong2 w2 = *(const ulonglong2*)&sW2[(c+2)*32 + o2];
            fma2(acc2[o2],   w2.x, vv2);  fma2(acc2[o2+1], w2.y, vv2);
            ulonglong2 w3 = *(const ulonglong2*)&sW2[(c+3)*32 + o2];
            fma2(acc2[o2],   w3.x, vv3);  fma2(acc2[o2+1], w3.y, vv3);
        }
    }
    float* yl = g_ylow + b*PL*PLOW + p;
#pragma unroll
    for (int o2 = 0; o2 < 32; o2++) {
        float lo, hi;
        upk2(lo, hi, acc2[o2]);
        yl[(2*o2)*PLOW]   = lo;
        yl[(2*o2+1)*PLOW] = hi;
    }
}

// ---------------------------------------------------------------------------
// K2: xv[b,o,h,w] = bilerp(y_low[b,o]) + sum_{g<64} W[o,256+g]*guide[b,g,h,w]
// Bilinear (scale 2, half-pixel): src = dst/2 - 0.25; edge renorm == clamp.
// ---------------------------------------------------------------------------
__global__ void __launch_bounds__(256) k_xv(const float* __restrict__ guide,
                                            const float* __restrict__ Wc) {
    __shared__ __align__(16) unsigned long long sW2[GC*32]; // [g][o2] pairs, 16 KB
    int tid = threadIdx.x;
    for (int i = tid; i < GC*32; i += 256) {
        int g  = i >> 5;
        int o2 = i & 31;
        sW2[i] = pk2(Wc[(2*o2)*WROW + CIN + g], Wc[(2*o2+1)*WROW + CIN + g]);
    }
    __syncthreads();

    int gp = blockIdx.x * 256 + tid;      // 0 .. BATCH*PFUL-1
    int b  = gp >> 16;
    int p  = gp & (PFUL-1);
    int h  = p >> 8, w = p & 255;

    // vertical taps
    int my = h >> 1; int y0, y1; float wy1;
    if (h & 1) { y0 = my; y1 = (my+1 < HL) ? my+1 : HL-1; wy1 = 0.25f; }
    else       { y1 = my; y0 = (my > 0)    ? my-1 : 0;    wy1 = 0.75f; }
    float wy0 = 1.f - wy1;
    // horizontal taps
    int mx = w >> 1; int x0, x1; float wx1;
    if (w & 1) { x0 = mx; x1 = (mx+1 < WL) ? mx+1 : WL-1; wx1 = 0.25f; }
    else       { x1 = mx; x0 = (mx > 0)    ? mx-1 : 0;    wx1 = 0.75f; }
    float wx0 = 1.f - wx1;

    int i00 = y0*WL + x0, i01 = y0*WL + x1, i10 = y1*WL + x0, i11 = y1*WL + x1;
    float w00 = wy0*wx0, w01 = wy0*wx1, w10 = wy1*wx0, w11 = wy1*wx1;

    const float* yl = g_ylow + b*PL*PLOW;
    unsigned long long acc2[32];
#pragma unroll
    for (int o2 = 0; o2 < 32; o2++) {
        const float* ya = yl + (2*o2)*PLOW;
        const float* yb = ya + PLOW;
        float lo = w00*ya[i00] + w01*ya[i01] + w10*ya[i10] + w11*ya[i11];
        float hi = w00*yb[i00] + w01*yb[i01] + w10*yb[i10] + w11*yb[i11];
        acc2[o2] = pk2(lo, hi);
    }

    const float* gb = guide + b*GC*PFUL + p;
    for (int g = 0; g < GC; g += 2) {
        unsigned long long vv0 = pk2(gb[(g+0)<<16], gb[(g+0)<<16]);
        unsigned long long vv1 = pk2(gb[(g+1)<<16], gb[(g+1)<<16]);
#pragma unroll
        for (int o2 = 0; o2 < 32; o2 += 2) {
            ulonglong2 w0 = *(const ulonglong2*)&sW2[(g+0)*32 + o2];
            fma2(acc2[o2],   w0.x, vv0);  fma2(acc2[o2+1], w0.y, vv0);
            ulonglong2 w1 = *(const ulonglong2*)&sW2[(g+1)*32 + o2];
            fma2(acc2[o2],   w1.x, vv1);  fma2(acc2[o2+1], w1.y, vv1);
        }
    }
    float* xvp = g_xv + b*PL*PFUL + p;
#pragma unroll
    for (int o2 = 0; o2 < 32; o2++) {
        float lo, hi;
        upk2(lo, hi, acc2[o2]);
        xvp[(2*o2)<<16]   = lo;
        xvp[(2*o2+1)<<16] = hi;
    }
}

// ---------------------------------------------------------------------------
// K3: 3x3 local attention (q=k=guide, v=xv), zero padding, writes pre-BN out.
// 16x16 pixel tile + halo; 128 threads, each handles a horizontal 2-pixel
// pair so one 3x4 window of LDS (12 loads) feeds both 9-tap stencils.
// ---------------------------------------------------------------------------
#define TILE_ELEMS (64*18*18)   // 20736
__global__ void __launch_bounds__(128) k_attn(const float* __restrict__ guide,
                                              float* __restrict__ out) {
    extern __shared__ float smem[];
    float* sG = smem;
    float* sV = smem + TILE_ELEMS;

    int b   = blockIdx.z;
    int x0t = blockIdx.x << 4;
    int y0t = blockIdx.y << 4;
    int tid = threadIdx.x;

    const float* gbase = guide + b*GC*PFUL;
    const float* vbase = g_xv  + b*PL*PFUL;

    for (int i = tid; i < TILE_ELEMS; i += 128) {
        int c   = i / 324;
        int rem = i - c*324;
        int r   = rem / 18;
        int col = rem - r*18;
        int gy = y0t + r - 1, gx = x0t + col - 1;
        float gv = 0.f, vv = 0.f;
        if ((unsigned)gy < 256u && (unsigned)gx < 256u) {
            int off = (c << 16) + (gy << 8) + gx;
            gv = gbase[off];
            vv = vbase[off];
        }
        sG[i] = gv;
        sV[i] = vv;
    }
    __syncthreads();

    int lx = tid & 7;            // pair index 0..7 -> pixels 2lx, 2lx+1
    int ly = tid >> 3;           // 0..15
    int base = (ly + 1)*18 + (2*lx + 1);   // smem index of px0 center

    float s0[9], s1[9];
#pragma unroll
    for (int t = 0; t < 9; t++) { s0[t] = 0.f; s1[t] = 0.f; }

    for (int c = 0; c < 64; c++) {
        const float* gc = sG + c*324 + base;
        float r0a = gc[-19], r0b = gc[-18], r0c = gc[-17], r0d = gc[-16];
        float r1a = gc[-1],  q0  = gc[0],   q1  = gc[1],   r1d = gc[2];
        float r2a = gc[17],  r2b = gc[18],  r2c = gc[19],  r2d = gc[20];
        s0[0] += q0*r0a; s0[1] += q0*r0b; s0[2] += q0*r0c;
        s0[3] += q0*r1a; s0[4] += q0*q0;  s0[5] += q0*q1;
        s0[6] += q0*r2a; s0[7] += q0*r2b; s0[8] += q0*r2c;
        s1[0] += q1*r0b; s1[1] += q1*r0c; s1[2] += q1*r0d;
        s1[3] += q1*q0;  s1[4] += q1*q1;  s1[5] += q1*r1d;
        s1[6] += q1*r2b; s1[7] += q1*r2c; s1[8] += q1*r2d;
    }

    float a0[9], a1[9];
    {
        float m = s0[0];
#pragma unroll
        for (int t = 1; t < 9; t++) m = fmaxf(m, s0[t]);
        float ssum = 0.f;
#pragma unroll
        for (int t = 0; t < 9; t++) { a0[t] = expf((s0[t] - m)*0.125f); ssum += a0[t]; }
        float inv = 1.f / ssum;
#pragma unroll
        for (int t = 0; t < 9; t++) a0[t] *= inv;
    }
    {
        float m = s1[0];
#pragma unroll
        for (int t = 1; t < 9; t++) m = fmaxf(m, s1[t]);
        float ssum = 0.f;
#pragma unroll
        for (int t = 0; t < 9; t++) { a1[t] = expf((s1[t] - m)*0.125f); ssum += a1[t]; }
        float inv = 1.f / ssum;
#pragma unroll
        for (int t = 0; t < 9; t++) a1[t] *= inv;
    }

    float* ob = out + b*PL*PFUL + ((y0t + ly) << 8) + (x0t + 2*lx);
    for (int o = 0; o < 64; o++) {
        const float* vc = sV + o*324 + base;
        float r0a = vc[-19], r0b = vc[-18], r0c = vc[-17], r0d = vc[-16];
        float r1a = vc[-1],  v0  = vc[0],   v1  = vc[1],   r1d = vc[2];
        float r2a = vc[17],  r2b = vc[18],  r2c = vc[19],  r2d = vc[20];
        float acc0 = a0[0]*r0a + a0[1]*r0b + a0[2]*r0c
                   + a0[3]*r1a + a0[4]*v0  + a0[5]*v1
                   + a0[6]*r2a + a0[7]*r2b + a0[8]*r2c;
        float acc1 = a1[0]*r0b + a1[1]*r0c + a1[2]*r0d
                   + a1[3]*v0  + a1[4]*v1  + a1[5]*r1d
                   + a1[6]*r2b + a1[7]*r2c + a1[8]*r2d;
        ob[(o << 16) + 0] = acc0;
        ob[(o << 16) + 1] = acc1;
    }
}

// ---------------------------------------------------------------------------
// K0: zero BN accumulators
// ---------------------------------------------------------------------------
__global__ void k_zero() {
    int i = threadIdx.x;
    if (i < PL) { g_sum[i] = 0.0; g_sumsq[i] = 0.0; }
}

// ---------------------------------------------------------------------------
// K3b: per-channel sum / sumsq reduction over (B,H,W)
// grid (64 channels, 16 slices); each block reduces 16384 contiguous floats.
// ---------------------------------------------------------------------------
__global__ void __launch_bounds__(256) k_stats(const float* __restrict__ out) {
    int o = blockIdx.x, s = blockIdx.y;
    int b = s >> 2;
    const float4* p4 = (const float4*)(out + ((b*PL + o) << 16) + ((s & 3) << 14));
    float sum = 0.f, ss = 0.f;
    for (int i = threadIdx.x; i < 4096; i += 256) {
        float4 v = p4[i];
        sum += v.x + v.y + v.z + v.w;
        ss  += v.x*v.x + v.y*v.y + v.z*v.z + v.w*v.w;
    }
#pragma unroll
    for (int d = 16; d; d >>= 1) {
        sum += __shfl_xor_sync(~0u, sum, d);
        ss  += __shfl_xor_sync(~0u, ss, d);
    }
    __shared__ float wsum[8], wss[8];
    int w = threadIdx.x >> 5;
    if ((threadIdx.x & 31) == 0) { wsum[w] = sum; wss[w] = ss; }
    __syncthreads();
    if (threadIdx.x == 0) {
        float ts = 0.f, tq = 0.f;
#pragma unroll
        for (int i = 0; i < 8; i++) { ts += wsum[i]; tq += wss[i]; }
        atomicAdd(&g_sum[o],   (double)ts);
        atomicAdd(&g_sumsq[o], (double)tq);
    }
}

// ---------------------------------------------------------------------------
// K4: finalize BN scale/shift (population variance, eps=1e-5)
// ---------------------------------------------------------------------------
__global__ void k_final(const float* __restrict__ gamma,
                        const float* __restrict__ beta) {
    int o = threadIdx.x;
    if (o < PL) {
        double N    = (double)(BATCH * PFUL);
        double mean = g_sum[o] / N;
        double var  = g_sumsq[o] / N - mean*mean;
        double sc   = (double)gamma[o] / sqrt(var + 1e-5);
        g_scale[o] = (float)sc;
        g_shift[o] = (float)((double)beta[o] - mean*sc);
    }
}

// ---------------------------------------------------------------------------
// K5: apply BN in place (float4, exact grid)
// ---------------------------------------------------------------------------
__global__ void __launch_bounds__(256) k_bn(float* __restrict__ out) {
    int i = blockIdx.x * 256 + threadIdx.x;   // float4 index; 4194304 total
    int o = (i >> 14) & 63;                   // 16384 float4 per channel
    float sc = g_scale[o], sh = g_shift[o];
    float4 v = ((float4*)out)[i];
    v.x = v.x*sc + sh; v.y = v.y*sc + sh;
    v.z = v.z*sc + sh; v.w = v.w*sc + sh;
    ((float4*)out)[i] = v;
}

// ---------------------------------------------------------------------------
extern "C" void kernel_launch(void* const* d_in, const int* in_sizes, int n_in,
                              void* d_out, int out_size) {
    const float* x     = (const float*)d_in[0];
    const float* guide = (const float*)d_in[1];
    const float* Wc    = (const float*)d_in[2];
    const float* gamma = (const float*)d_in[3];
    const float* beta  = (const float*)d_in[4];
    float* out = (float*)d_out;

    const int conv_smem = CIN*32*(int)sizeof(unsigned long long);  // 65536 B
    const int attn_smem = 2 * TILE_ELEMS * (int)sizeof(float);     // 165888 B
    cudaFuncSetAttribute(k_conv_low, cudaFuncAttributeMaxDynamicSharedMemorySize, conv_smem);
    cudaFuncSetAttribute(k_attn,     cudaFuncAttributeMaxDynamicSharedMemorySize, attn_smem);

    k_conv_low<<<(BATCH*PLOW)/128, 128, conv_smem>>>(x, Wc);
    k_xv<<<(BATCH*PFUL)/256, 256>>>(guide, Wc);
    k_zero<<<1, 64>>>();
    k_attn<<<dim3(WW/16, HH/16, BATCH), 128, attn_smem>>>(guide, out);
    k_stats<<<dim3(PL, 16), 256>>>(out);
    k_final<<<1, 64>>>(gamma, beta);
    k_bn<<<(BATCH*PL*PFUL)/4/256, 256>>>(out);
}

// round 6
// speedup vs baseline: 1.0492x; 1.0492x over previous
#include <cuda_runtime.h>
#include <math.h>

// Shapes (compile-time constants for this problem instance)
#define BATCH 4
#define CIN   256
#define GC    64
#define PL    64
#define HL    128
#define WL    128
#define HH    256
#define WW    256
#define PLOW  (HL*WL)        // 16384
#define PFUL  (HH*WW)        // 65536
#define WROW  (CIN+GC)       // 320

// Scratch (device globals — no allocations allowed)
__device__ float  g_ylow[BATCH*PL*PLOW];   // 16 MB: conv1x1 of x at low res
__device__ float  g_xv[BATCH*PL*PFUL];     // 64 MB: v = upsample(ylow) + Wg*guide
__device__ double g_sum[PL];
__device__ double g_sumsq[PL];
__device__ float  g_scale[PL];
__device__ float  g_shift[PL];

// ---- packed fp32x2 helpers (sm_100+ dual-lane fp32; full fp32 precision) ----
__device__ __forceinline__ unsigned long long pk2(float lo, float hi) {
    unsigned long long r;
    asm("mov.b64 %0, {%1, %2};" : "=l"(r) : "f"(lo), "f"(hi));
    return r;
}
__device__ __forceinline__ void upk2(float& lo, float& hi, unsigned long long v) {
    asm("mov.b64 {%0, %1}, %2;" : "=f"(lo), "=f"(hi) : "l"(v));
}
__device__ __forceinline__ void fma2(unsigned long long& d,
                                     unsigned long long a, unsigned long long b) {
    asm("fma.rn.f32x2 %0, %1, %2, %0;" : "+l"(d) : "l"(a), "l"(b));
}

// ---------------------------------------------------------------------------
// K1: y_low[b,o,p] = sum_{c<256} W[o,c] * x[b,c,p]    (GEMM M=64,K=256,N=65536)
// ---------------------------------------------------------------------------
__global__ void __launch_bounds__(128) k_conv_low(const float* __restrict__ x,
                                                  const float* __restrict__ Wc) {
    extern __shared__ unsigned long long sW2[];   // [CIN][32] packed pairs
    int tid = threadIdx.x;
    for (int i = tid; i < CIN*32; i += 128) {
        int c  = i >> 5;        // 0..255
        int o2 = i & 31;        // pair index
        sW2[i] = pk2(Wc[(2*o2)*WROW + c], Wc[(2*o2+1)*WROW + c]);
    }
    __syncthreads();

    int gp = blockIdx.x * 128 + tid;      // 0 .. BATCH*PLOW-1
    int b  = gp >> 14;                    // /16384
    int p  = gp & (PLOW-1);
    const float* xb = x + b*CIN*PLOW + p;

    unsigned long long acc2[32];
#pragma unroll
    for (int o = 0; o < 32; o++) acc2[o] = 0ULL;

    for (int c = 0; c < CIN; c += 4) {
        unsigned long long vv0 = pk2(xb[(c+0)*PLOW], xb[(c+0)*PLOW]);
        unsigned long long vv1 = pk2(xb[(c+1)*PLOW], xb[(c+1)*PLOW]);
        unsigned long long vv2 = pk2(xb[(c+2)*PLOW], xb[(c+2)*PLOW]);
        unsigned long long vv3 = pk2(xb[(c+3)*PLOW], xb[(c+3)*PLOW]);
#pragma unroll
        for (int o2 = 0; o2 < 32; o2 += 2) {
            ulonglong2 w0 = *(const ulonglong2*)&sW2[(c+0)*32 + o2];
            fma2(acc2[o2],   w0.x, vv0);  fma2(acc2[o2+1], w0.y, vv0);
            ulonglong2 w1 = *(const ulonglong2*)&sW2[(c+1)*32 + o2];
            fma2(acc2[o2],   w1.x, vv1);  fma2(acc2[o2+1], w1.y, vv1);
            ulonglong2 w2 = *(const ulonglong2*)&sW2[(c+2)*32 + o2];
            fma2(acc2[o2],   w2.x, vv2);  fma2(acc2[o2+1], w2.y, vv2);
            ulonglong2 w3 = *(const ulonglong2*)&sW2[(c+3)*32 + o2];
            fma2(acc2[o2],   w3.x, vv3);  fma2(acc2[o2+1], w3.y, vv3);
        }
    }
    float* yl = g_ylow + b*PL*PLOW + p;
#pragma unroll
    for (int o2 = 0; o2 < 32; o2++) {
        float lo, hi;
        upk2(lo, hi, acc2[o2]);
        yl[(2*o2)*PLOW]   = lo;
        yl[(2*o2+1)*PLOW] = hi;
    }
}

// ---------------------------------------------------------------------------
// K2: xv[b,o,h,w] = bilerp(y_low[b,o]) + sum_{g<64} W[o,256+g]*guide[b,g,h,w]
// ---------------------------------------------------------------------------
__global__ void __launch_bounds__(256) k_xv(const float* __restrict__ guide,
                                            const float* __restrict__ Wc) {
    __shared__ __align__(16) unsigned long long sW2[GC*32]; // [g][o2] pairs, 16 KB
    int tid = threadIdx.x;
    for (int i = tid; i < GC*32; i += 256) {
        int g  = i >> 5;
        int o2 = i & 31;
        sW2[i] = pk2(Wc[(2*o2)*WROW + CIN + g], Wc[(2*o2+1)*WROW + CIN + g]);
    }
    __syncthreads();

    int gp = blockIdx.x * 256 + tid;      // 0 .. BATCH*PFUL-1
    int b  = gp >> 16;
    int p  = gp & (PFUL-1);
    int h  = p >> 8, w = p & 255;

    // vertical taps
    int my = h >> 1; int y0, y1; float wy1;
    if (h & 1) { y0 = my; y1 = (my+1 < HL) ? my+1 : HL-1; wy1 = 0.25f; }
    else       { y1 = my; y0 = (my > 0)    ? my-1 : 0;    wy1 = 0.75f; }
    float wy0 = 1.f - wy1;
    // horizontal taps
    int mx = w >> 1; int x0, x1; float wx1;
    if (w & 1) { x0 = mx; x1 = (mx+1 < WL) ? mx+1 : WL-1; wx1 = 0.25f; }
    else       { x1 = mx; x0 = (mx > 0)    ? mx-1 : 0;    wx1 = 0.75f; }
    float wx0 = 1.f - wx1;

    int i00 = y0*WL + x0, i01 = y0*WL + x1, i10 = y1*WL + x0, i11 = y1*WL + x1;
    float w00 = wy0*wx0, w01 = wy0*wx1, w10 = wy1*wx0, w11 = wy1*wx1;

    const float* yl = g_ylow + b*PL*PLOW;
    unsigned long long acc2[32];
#pragma unroll
    for (int o2 = 0; o2 < 32; o2++) {
        const float* ya = yl + (2*o2)*PLOW;
        const float* yb = ya + PLOW;
        float lo = w00*ya[i00] + w01*ya[i01] + w10*ya[i10] + w11*ya[i11];
        float hi = w00*yb[i00] + w01*yb[i01] + w10*yb[i10] + w11*yb[i11];
        acc2[o2] = pk2(lo, hi);
    }

    const float* gb = guide + b*GC*PFUL + p;
    for (int g = 0; g < GC; g += 2) {
        unsigned long long vv0 = pk2(gb[(g+0)<<16], gb[(g+0)<<16]);
        unsigned long long vv1 = pk2(gb[(g+1)<<16], gb[(g+1)<<16]);
#pragma unroll
        for (int o2 = 0; o2 < 32; o2 += 2) {
            ulonglong2 w0 = *(const ulonglong2*)&sW2[(g+0)*32 + o2];
            fma2(acc2[o2],   w0.x, vv0);  fma2(acc2[o2+1], w0.y, vv0);
            ulonglong2 w1 = *(const ulonglong2*)&sW2[(g+1)*32 + o2];
            fma2(acc2[o2],   w1.x, vv1);  fma2(acc2[o2+1], w1.y, vv1);
        }
    }
    float* xvp = g_xv + b*PL*PFUL + p;
#pragma unroll
    for (int o2 = 0; o2 < 32; o2++) {
        float lo, hi;
        upk2(lo, hi, acc2[o2]);
        xvp[(2*o2)<<16]   = lo;
        xvp[(2*o2+1)<<16] = hi;
    }
}

// ---------------------------------------------------------------------------
// K3: 3x3 local attention (q=k=guide, v=xv), zero padding, writes pre-BN out.
// v2: only the GUIDE tile lives in smem (83 KB -> 2 blocks/SM, 16 warps/SM).
// V is read straight from g_xv in the output loop: clamped offsets +
// pre-masked weights keep every load in-bounds and branch-free; within a
// block the 9-tap windows overlap so V reads are L1-resident.
// ---------------------------------------------------------------------------
#define GT_ELEMS (64*18*18)   // 20736 floats = 82944 B
__global__ void __launch_bounds__(256) k_attn(const float* __restrict__ guide,
                                              float* __restrict__ out) {
    extern __shared__ float sG[];

    int b   = blockIdx.z;
    int x0t = blockIdx.x << 4;
    int y0t = blockIdx.y << 4;
    int tid = threadIdx.x;

    const float* gbase = guide + b*GC*PFUL;

    for (int i = tid; i < GT_ELEMS; i += 256) {
        int c   = i / 324;
        int rem = i - c*324;
        int r   = rem / 18;
        int col = rem - r*18;
        int gy = y0t + r - 1, gx = x0t + col - 1;
        float gv = 0.f;
        if ((unsigned)gy < 256u && (unsigned)gx < 256u)
            gv = gbase[(c << 16) + (gy << 8) + gx];
        sG[i] = gv;
    }
    __syncthreads();

    int lx = tid & 15, ly = tid >> 4;
    int base = (ly + 1)*18 + (lx + 1);

    float s[9];
#pragma unroll
    for (int t = 0; t < 9; t++) s[t] = 0.f;

#pragma unroll 2
    for (int c = 0; c < 64; c++) {
        const float* gc = sG + c*324 + base;
        float q = gc[0];
        s[0] += q * gc[-19];
        s[1] += q * gc[-18];
        s[2] += q * gc[-17];
        s[3] += q * gc[-1];
        s[4] += q * q;
        s[5] += q * gc[1];
        s[6] += q * gc[17];
        s[7] += q * gc[18];
        s[8] += q * gc[19];
    }

    float m = s[0];
#pragma unroll
    for (int t = 1; t < 9; t++) m = fmaxf(m, s[t]);
    float a[9], ssum = 0.f;
#pragma unroll
    for (int t = 0; t < 9; t++) { a[t] = expf((s[t] - m)*0.125f); ssum += a[t]; }
    float inv = 1.f / ssum;

    // clamped tap offsets + masked weights (zero-pad semantics, in-bounds loads)
    int gy = y0t + ly, gx = x0t + lx;
    int off[9];
#pragma unroll
    for (int t = 0; t < 9; t++) {
        int dy = t/3 - 1, dx = t%3 - 1;
        int yy = gy + dy, xx = gx + dx;
        bool ok = ((unsigned)yy < 256u) && ((unsigned)xx < 256u);
        int yc = ok ? yy : gy;
        int xc = ok ? xx : gx;
        off[t] = (yc << 8) + xc;
        a[t] = ok ? a[t]*inv : 0.f;
    }

    const float* vb = g_xv + b*PL*PFUL;
    float* ob = out + b*PL*PFUL + (gy << 8) + gx;
#pragma unroll 2
    for (int o = 0; o < 64; o++) {
        const float* vc = vb + (o << 16);
        float acc = a[0]*vc[off[0]] + a[1]*vc[off[1]] + a[2]*vc[off[2]]
                  + a[3]*vc[off[3]] + a[4]*vc[off[4]] + a[5]*vc[off[5]]
                  + a[6]*vc[off[6]] + a[7]*vc[off[7]] + a[8]*vc[off[8]];
        ob[o << 16] = acc;
    }
}

// ---------------------------------------------------------------------------
// K0: zero BN accumulators
// ---------------------------------------------------------------------------
__global__ void k_zero() {
    int i = threadIdx.x;
    if (i < PL) { g_sum[i] = 0.0; g_sumsq[i] = 0.0; }
}

// ---------------------------------------------------------------------------
// K3b: per-channel sum / sumsq reduction over (B,H,W)
// ---------------------------------------------------------------------------
__global__ void __launch_bounds__(256) k_stats(const float* __restrict__ out) {
    int o = blockIdx.x, s = blockIdx.y;
    int b = s >> 2;
    const float4* p4 = (const float4*)(out + ((b*PL + o) << 16) + ((s & 3) << 14));
    float sum = 0.f, ss = 0.f;
    for (int i = threadIdx.x; i < 4096; i += 256) {
        float4 v = p4[i];
        sum += v.x + v.y + v.z + v.w;
        ss  += v.x*v.x + v.y*v.y + v.z*v.z + v.w*v.w;
    }
#pragma unroll
    for (int d = 16; d; d >>= 1) {
        sum += __shfl_xor_sync(~0u, sum, d);
        ss  += __shfl_xor_sync(~0u, ss, d);
    }
    __shared__ float wsum[8], wss[8];
    int w = threadIdx.x >> 5;
    if ((threadIdx.x & 31) == 0) { wsum[w] = sum; wss[w] = ss; }
    __syncthreads();
    if (threadIdx.x == 0) {
        float ts = 0.f, tq = 0.f;
#pragma unroll
        for (int i = 0; i < 8; i++) { ts += wsum[i]; tq += wss[i]; }
        atomicAdd(&g_sum[o],   (double)ts);
        atomicAdd(&g_sumsq[o], (double)tq);
    }
}

// ---------------------------------------------------------------------------
// K4: finalize BN scale/shift (population variance, eps=1e-5)
// ---------------------------------------------------------------------------
__global__ void k_final(const float* __restrict__ gamma,
                        const float* __restrict__ beta) {
    int o = threadIdx.x;
    if (o < PL) {
        double N    = (double)(BATCH * PFUL);
        double mean = g_sum[o] / N;
        double var  = g_sumsq[o] / N - mean*mean;
        double sc   = (double)gamma[o] / sqrt(var + 1e-5);
        g_scale[o] = (float)sc;
        g_shift[o] = (float)((double)beta[o] - mean*sc);
    }
}

// ---------------------------------------------------------------------------
// K5: apply BN in place (float4, exact grid)
// ---------------------------------------------------------------------------
__global__ void __launch_bounds__(256) k_bn(float* __restrict__ out) {
    int i = blockIdx.x * 256 + threadIdx.x;   // float4 index; 4194304 total
    int o = (i >> 14) & 63;                   // 16384 float4 per channel
    float sc = g_scale[o], sh = g_shift[o];
    float4 v = ((float4*)out)[i];
    v.x = v.x*sc + sh; v.y = v.y*sc + sh;
    v.z = v.z*sc + sh; v.w = v.w*sc + sh;
    ((float4*)out)[i] = v;
}

// ---------------------------------------------------------------------------
extern "C" void kernel_launch(void* const* d_in, const int* in_sizes, int n_in,
                              void* d_out, int out_size) {
    const float* x     = (const float*)d_in[0];
    const float* guide = (const float*)d_in[1];
    const float* Wc    = (const float*)d_in[2];
    const float* gamma = (const float*)d_in[3];
    const float* beta  = (const float*)d_in[4];
    float* out = (float*)d_out;

    const int conv_smem = CIN*32*(int)sizeof(unsigned long long);  // 65536 B
    const int attn_smem = GT_ELEMS * (int)sizeof(float);           // 82944 B
    cudaFuncSetAttribute(k_conv_low, cudaFuncAttributeMaxDynamicSharedMemorySize, conv_smem);
    cudaFuncSetAttribute(k_attn,     cudaFuncAttributeMaxDynamicSharedMemorySize, attn_smem);

    k_conv_low<<<(BATCH*PLOW)/128, 128, conv_smem>>>(x, Wc);
    k_xv<<<(BATCH*PFUL)/256, 256>>>(guide, Wc);
    k_zero<<<1, 64>>>();
    k_attn<<<dim3(WW/16, HH/16, BATCH), 256, attn_smem>>>(guide, out);
    k_stats<<<dim3(PL, 16), 256>>>(out);
    k_final<<<1, 64>>>(gamma, beta);
    k_bn<<<(BATCH*PL*PFUL)/4/256, 256>>>(out);
}

// round 10
// speedup vs baseline: 1.5557x; 1.4828x over previous
#include <cuda_runtime.h>
#include <math.h>

// Shapes (compile-time constants for this problem instance)
#define BATCH 4
#define CIN   256
#define GC    64
#define PL    64
#define HL    128
#define WL    128
#define HH    256
#define WW    256
#define PLOW  (HL*WL)        // 16384
#define PFUL  (HH*WW)        // 65536
#define WROW  (CIN+GC)       // 320

// Scratch (device globals — no allocations allowed)
__device__ float  g_ylow[BATCH*PL*PLOW];   // 16 MB: conv1x1 of x at low res
__device__ float  g_xv[BATCH*PL*PFUL];     // 64 MB: v = upsample(ylow) + Wg*guide
__device__ double g_sum[PL];
__device__ double g_sumsq[PL];
__device__ float  g_scale[PL];
__device__ float  g_shift[PL];

// ---- packed fp32x2 helpers (sm_100+ dual-lane fp32; full fp32 precision) ----
__device__ __forceinline__ unsigned long long pk2(float lo, float hi) {
    unsigned long long r;
    asm("mov.b64 %0, {%1, %2};" : "=l"(r) : "f"(lo), "f"(hi));
    return r;
}
__device__ __forceinline__ void upk2(float& lo, float& hi, unsigned long long v) {
    asm("mov.b64 {%0, %1}, %2;" : "=f"(lo), "=f"(hi) : "l"(v));
}
__device__ __forceinline__ void fma2(unsigned long long& d,
                                     unsigned long long a, unsigned long long b) {
    asm("fma.rn.f32x2 %0, %1, %2, %0;" : "+l"(d) : "l"(a), "l"(b));
}

// ---------------------------------------------------------------------------
// K1: y_low[b,o,p] = sum_{c<256} W[o,c] * x[b,c,p]    (GEMM M=64,K=256,N=65536)
// o-split across blockIdx.y: each block computes 32 outputs (16 f32x2 pairs).
// smem 32 KB, acc2[16] -> ~28 warps/SM.
// ---------------------------------------------------------------------------
__global__ void __launch_bounds__(128) k_conv_low(const float* __restrict__ x,
                                                  const float* __restrict__ Wc) {
    extern __shared__ unsigned long long sW2[];   // [CIN][16] packed pairs, 32 KB
    int tid = threadIdx.x;
    int oh  = blockIdx.y;                 // 0/1 -> o2 in [16*oh, 16*oh+16)
    for (int i = tid; i < CIN*16; i += 128) {
        int c   = i >> 4;                 // 0..255
        int o2  = 16*oh + (i & 15);
        sW2[i] = pk2(Wc[(2*o2)*WROW + c], Wc[(2*o2+1)*WROW + c]);
    }
    __syncthreads();

    int gp = blockIdx.x * 128 + tid;      // 0 .. BATCH*PLOW-1
    int b  = gp >> 14;
    int p  = gp & (PLOW-1);
    const float* xb = x + b*CIN*PLOW + p;

    unsigned long long acc2[16];
#pragma unroll
    for (int o = 0; o < 16; o++) acc2[o] = 0ULL;

    for (int c = 0; c < CIN; c += 4) {
        unsigned long long vv0 = pk2(xb[(c+0)*PLOW], xb[(c+0)*PLOW]);
        unsigned long long vv1 = pk2(xb[(c+1)*PLOW], xb[(c+1)*PLOW]);
        unsigned long long vv2 = pk2(xb[(c+2)*PLOW], xb[(c+2)*PLOW]);
        unsigned long long vv3 = pk2(xb[(c+3)*PLOW], xb[(c+3)*PLOW]);
#pragma unroll
        for (int o2 = 0; o2 < 16; o2 += 2) {
            ulonglong2 w0 = *(const ulonglong2*)&sW2[(c+0)*16 + o2];
            fma2(acc2[o2],   w0.x, vv0);  fma2(acc2[o2+1], w0.y, vv0);
            ulonglong2 w1 = *(const ulonglong2*)&sW2[(c+1)*16 + o2];
            fma2(acc2[o2],   w1.x, vv1);  fma2(acc2[o2+1], w1.y, vv1);
            ulonglong2 w2 = *(const ulonglong2*)&sW2[(c+2)*16 + o2];
            fma2(acc2[o2],   w2.x, vv2);  fma2(acc2[o2+1], w2.y, vv2);
            ulonglong2 w3 = *(const ulonglong2*)&sW2[(c+3)*16 + o2];
            fma2(acc2[o2],   w3.x, vv3);  fma2(acc2[o2+1], w3.y, vv3);
        }
    }
    float* yl = g_ylow + b*PL*PLOW + p;
#pragma unroll
    for (int o2 = 0; o2 < 16; o2++) {
        float lo, hi;
        upk2(lo, hi, acc2[o2]);
        int o = 2*(16*oh + o2);
        yl[o*PLOW]       = lo;
        yl[(o+1)*PLOW]   = hi;
    }
}

// ---------------------------------------------------------------------------
// K2: xv[b,o,h,w] = bilerp(y_low[b,o]) + sum_{g<64} W[o,256+g]*guide[b,g,h,w]
// o-split across blockIdx.y: 32 outputs per block, acc2[16].
// ---------------------------------------------------------------------------
__global__ void __launch_bounds__(256) k_xv(const float* __restrict__ guide,
                                            const float* __restrict__ Wc) {
    __shared__ __align__(16) unsigned long long sW2[GC*16];  // 8 KB
    int tid = threadIdx.x;
    int oh  = blockIdx.y;
    for (int i = tid; i < GC*16; i += 256) {
        int g  = i >> 4;
        int o2 = 16*oh + (i & 15);
        sW2[i] = pk2(Wc[(2*o2)*WROW + CIN + g], Wc[(2*o2+1)*WROW + CIN + g]);
    }
    __syncthreads();

    int gp = blockIdx.x * 256 + tid;      // 0 .. BATCH*PFUL-1
    int b  = gp >> 16;
    int p  = gp & (PFUL-1);
    int h  = p >> 8, w = p & 255;

    // vertical taps
    int my = h >> 1; int y0, y1; float wy1;
    if (h & 1) { y0 = my; y1 = (my+1 < HL) ? my+1 : HL-1; wy1 = 0.25f; }
    else       { y1 = my; y0 = (my > 0)    ? my-1 : 0;    wy1 = 0.75f; }
    float wy0 = 1.f - wy1;
    // horizontal taps
    int mx = w >> 1; int x0, x1; float wx1;
    if (w & 1) { x0 = mx; x1 = (mx+1 < WL) ? mx+1 : WL-1; wx1 = 0.25f; }
    else       { x1 = mx; x0 = (mx > 0)    ? mx-1 : 0;    wx1 = 0.75f; }
    float wx0 = 1.f - wx1;

    int i00 = y0*WL + x0, i01 = y0*WL + x1, i10 = y1*WL + x0, i11 = y1*WL + x1;
    float w00 = wy0*wx0, w01 = wy0*wx1, w10 = wy1*wx0, w11 = wy1*wx1;

    const float* yl = g_ylow + b*PL*PLOW;
    unsigned long long acc2[16];
#pragma unroll
    for (int o2 = 0; o2 < 16; o2++) {
        const float* ya = yl + 2*(16*oh + o2)*PLOW;
        const float* yb = ya + PLOW;
        float lo = w00*ya[i00] + w01*ya[i01] + w10*ya[i10] + w11*ya[i11];
        float hi = w00*yb[i00] + w01*yb[i01] + w10*yb[i10] + w11*yb[i11];
        acc2[o2] = pk2(lo, hi);
    }

    const float* gb = guide + b*GC*PFUL + p;
    for (int g = 0; g < GC; g += 2) {
        unsigned long long vv0 = pk2(gb[(g+0)<<16], gb[(g+0)<<16]);
        unsigned long long vv1 = pk2(gb[(g+1)<<16], gb[(g+1)<<16]);
#pragma unroll
        for (int o2 = 0; o2 < 16; o2 += 2) {
            ulonglong2 w0 = *(const ulonglong2*)&sW2[(g+0)*16 + o2];
            fma2(acc2[o2],   w0.x, vv0);  fma2(acc2[o2+1], w0.y, vv0);
            ulonglong2 w1 = *(const ulonglong2*)&sW2[(g+1)*16 + o2];
            fma2(acc2[o2],   w1.x, vv1);  fma2(acc2[o2+1], w1.y, vv1);
        }
    }
    float* xvp = g_xv + b*PL*PFUL + p;
#pragma unroll
    for (int o2 = 0; o2 < 16; o2++) {
        float lo, hi;
        upk2(lo, hi, acc2[o2]);
        int o = 2*(16*oh + o2);
        xvp[o<<16]     = lo;
        xvp[(o+1)<<16] = hi;
    }
}

// ---------------------------------------------------------------------------
// K3: 3x3 local attention. Channel-chunked guide tile (16 ch = 20.7 KB) so
// occupancy is reg-capped (~40 warps/SM). Scores accumulate across 4 chunks;
// V read direct from gmem via 9 pre-clamped tap pointers + masked weights
// (zero-pad semantics preserved).
// ---------------------------------------------------------------------------
#define ACH 16
#define ATILE_ELEMS (ACH*18*18)   // 5184 floats = 20736 B
__global__ void __launch_bounds__(256) k_attn(const float* __restrict__ guide,
                                              float* __restrict__ out) {
    extern __shared__ float sG[];

    int b   = blockIdx.z;
    int x0t = blockIdx.x << 4;
    int y0t = blockIdx.y << 4;
    int tid = threadIdx.x;

    int lx = tid & 15, ly = tid >> 4;
    int base = (ly + 1)*18 + (lx + 1);

    const float* gbase = guide + b*GC*PFUL;

    float s[9];
#pragma unroll
    for (int t = 0; t < 9; t++) s[t] = 0.f;

    for (int ch = 0; ch < GC; ch += ACH) {
        __syncthreads();   // previous chunk fully consumed
        for (int i = tid; i < ATILE_ELEMS; i += 256) {
            int c   = i / 324;                 // local channel 0..15
            int rem = i - c*324;
            int r   = rem / 18;
            int col = rem - r*18;
            int gy = y0t + r - 1, gx = x0t + col - 1;
            float gv = 0.f;
            if ((unsigned)gy < 256u && (unsigned)gx < 256u)
                gv = gbase[((ch + c) << 16) + (gy << 8) + gx];
            sG[i] = gv;
        }
        __syncthreads();

#pragma unroll 2
        for (int c = 0; c < ACH; c++) {
            const float* gc = sG + c*324 + base;
            float q = gc[0];
            s[0] += q * gc[-19];
            s[1] += q * gc[-18];
            s[2] += q * gc[-17];
            s[3] += q * gc[-1];
            s[4] += q * q;
            s[5] += q * gc[1];
            s[6] += q * gc[17];
            s[7] += q * gc[18];
            s[8] += q * gc[19];
        }
    }

    float m = s[0];
#pragma unroll
    for (int t = 1; t < 9; t++) m = fmaxf(m, s[t]);
    float a[9], ssum = 0.f;
#pragma unroll
    for (int t = 0; t < 9; t++) { a[t] = expf((s[t] - m)*0.125f); ssum += a[t]; }
    float inv = 1.f / ssum;

    // clamped tap pointers + masked weights (zero-pad semantics, in-bounds loads)
    int gy = y0t + ly, gx = x0t + lx;
    const float* vb = g_xv + b*PL*PFUL;
    const float* vt[9];
#pragma unroll
    for (int t = 0; t < 9; t++) {
        int dy = t/3 - 1, dx = t%3 - 1;
        int yy = gy + dy, xx = gx + dx;
        bool ok = ((unsigned)yy < 256u) && ((unsigned)xx < 256u);
        int yc = ok ? yy : gy;
        int xc = ok ? xx : gx;
        vt[t] = vb + (yc << 8) + xc;
        a[t] = ok ? a[t]*inv : 0.f;
    }

    float* ob = out + b*PL*PFUL + (gy << 8) + gx;
#pragma unroll 2
    for (int o = 0; o < 64; o++) {
        int co = o << 16;
        float acc = a[0]*vt[0][co] + a[1]*vt[1][co] + a[2]*vt[2][co]
                  + a[3]*vt[3][co] + a[4]*vt[4][co] + a[5]*vt[5][co]
                  + a[6]*vt[6][co] + a[7]*vt[7][co] + a[8]*vt[8][co];
        ob[co] = acc;
    }
}

// ---------------------------------------------------------------------------
// K0: zero BN accumulators
// ---------------------------------------------------------------------------
__global__ void k_zero() {
    int i = threadIdx.x;
    if (i < PL) { g_sum[i] = 0.0; g_sumsq[i] = 0.0; }
}

// ---------------------------------------------------------------------------
// K3b: per-channel sum / sumsq reduction over (B,H,W)
// grid (64, 32): each block reduces 8192 contiguous floats of one channel.
// ---------------------------------------------------------------------------
__global__ void __launch_bounds__(256) k_stats(const float* __restrict__ out) {
    int o = blockIdx.x, s = blockIdx.y;      // s: 0..31, 8 slices per image
    int b = s >> 3;
    const float4* p4 = (const float4*)(out + ((b*PL + o) << 16) + ((s & 7) << 13));
    float sum = 0.f, ss = 0.f;
    for (int i = threadIdx.x; i < 2048; i += 256) {
        float4 v = p4[i];
        sum += v.x + v.y + v.z + v.w;
        ss  += v.x*v.x + v.y*v.y + v.z*v.z + v.w*v.w;
    }
#pragma unroll
    for (int d = 16; d; d >>= 1) {
        sum += __shfl_xor_sync(~0u, sum, d);
        ss  += __shfl_xor_sync(~0u, ss, d);
    }
    __shared__ float wsum[8], wss[8];
    int w = threadIdx.x >> 5;
    if ((threadIdx.x & 31) == 0) { wsum[w] = sum; wss[w] = ss; }
    __syncthreads();
    if (threadIdx.x == 0) {
        float ts = 0.f, tq = 0.f;
#pragma unroll
        for (int i = 0; i < 8; i++) { ts += wsum[i]; tq += wss[i]; }
        atomicAdd(&g_sum[o],   (double)ts);
        atomicAdd(&g_sumsq[o], (double)tq);
    }
}

// ---------------------------------------------------------------------------
// K4: finalize BN scale/shift (population variance, eps=1e-5)
// ---------------------------------------------------------------------------
__global__ void k_final(const float* __restrict__ gamma,
                        const float* __restrict__ beta) {
    int o = threadIdx.x;
    if (o < PL) {
        double N    = (double)(BATCH * PFUL);
        double mean = g_sum[o] / N;
        double var  = g_sumsq[o] / N - mean*mean;
        double sc   = (double)gamma[o] / sqrt(var + 1e-5);
        g_scale[o] = (float)sc;
        g_shift[o] = (float)((double)beta[o] - mean*sc);
    }
}

// ---------------------------------------------------------------------------
// K5: apply BN in place (float4, exact grid)
// ---------------------------------------------------------------------------
__global__ void __launch_bounds__(256) k_bn(float* __restrict__ out) {
    int i = blockIdx.x * 256 + threadIdx.x;   // float4 index; 4194304 total
    int o = (i >> 14) & 63;                   // 16384 float4 per channel
    float sc = g_scale[o], sh = g_shift[o];
    float4 v = ((float4*)out)[i];
    v.x = v.x*sc + sh; v.y = v.y*sc + sh;
    v.z = v.z*sc + sh; v.w = v.w*sc + sh;
    ((float4*)out)[i] = v;
}

// ---------------------------------------------------------------------------
extern "C" void kernel_launch(void* const* d_in, const int* in_sizes, int n_in,
                              void* d_out, int out_size) {
    const float* x     = (const float*)d_in[0];
    const float* guide = (const float*)d_in[1];
    const float* Wc    = (const float*)d_in[2];
    const float* gamma = (const float*)d_in[3];
    const float* beta  = (const float*)d_in[4];
    float* out = (float*)d_out;

    const int conv_smem = CIN*16*(int)sizeof(unsigned long long);   // 32768 B
    const int attn_smem = ATILE_ELEMS * (int)sizeof(float);         // 20736 B
    cudaFuncSetAttribute(k_conv_low, cudaFuncAttributeMaxDynamicSharedMemorySize, conv_smem);
    cudaFuncSetAttribute(k_attn,     cudaFuncAttributeMaxDynamicSharedMemorySize, attn_smem);

    k_conv_low<<<dim3((BATCH*PLOW)/128, 2), 128, conv_smem>>>(x, Wc);
    k_xv<<<dim3((BATCH*PFUL)/256, 2), 256>>>(guide, Wc);
    k_zero<<<1, 64>>>();
    k_attn<<<dim3(WW/16, HH/16, BATCH), 256, attn_smem>>>(guide, out);
    k_stats<<<dim3(PL, 32), 256>>>(out);
    k_final<<<1, 64>>>(gamma, beta);
    k_bn<<<(BATCH*PL*PFUL)/4/256, 256>>>(out);
}

// round 11
// speedup vs baseline: 1.6625x; 1.0687x over previous
#include <cuda_runtime.h>
#include <math.h>

// Shapes (compile-time constants for this problem instance)
#define BATCH 4
#define CIN   256
#define GC    64
#define PL    64
#define HL    128
#define WL    128
#define HH    256
#define WW    256
#define PLOW  (HL*WL)        // 16384
#define PFUL  (HH*WW)        // 65536
#define WROW  (CIN+GC)       // 320

// Scratch (device globals — no allocations allowed)
__device__ float  g_ylow[BATCH*PL*PLOW];   // 16 MB: conv1x1 of x at low res
__device__ float  g_xv[BATCH*PL*PFUL];     // 64 MB: v = upsample(ylow) + Wg*guide
__device__ double g_sum[PL];
__device__ double g_sumsq[PL];
__device__ float  g_scale[PL];
__device__ float  g_shift[PL];

// ---- packed fp32x2 helpers (sm_100+ dual-lane fp32; full fp32 precision) ----
__device__ __forceinline__ unsigned long long pk2(float lo, float hi) {
    unsigned long long r;
    asm("mov.b64 %0, {%1, %2};" : "=l"(r) : "f"(lo), "f"(hi));
    return r;
}
__device__ __forceinline__ void upk2(float& lo, float& hi, unsigned long long v) {
    asm("mov.b64 {%0, %1}, %2;" : "=f"(lo), "=f"(hi) : "l"(v));
}
__device__ __forceinline__ void fma2(unsigned long long& d,
                                     unsigned long long a, unsigned long long b) {
    asm("fma.rn.f32x2 %0, %1, %2, %0;" : "+l"(d) : "l"(a), "l"(b));
}

// ---------------------------------------------------------------------------
// K1: y_low[b,o,p] = sum_{c<256} W[o,c] * x[b,c,p]    (GEMM M=64,K=256,N=65536)
// o-split across blockIdx.y: each block computes 32 outputs (16 f32x2 pairs).
// ---------------------------------------------------------------------------
__global__ void __launch_bounds__(128) k_conv_low(const float* __restrict__ x,
                                                  const float* __restrict__ Wc) {
    extern __shared__ unsigned long long sW2[];   // [CIN][16] packed pairs, 32 KB
    int tid = threadIdx.x;
    int oh  = blockIdx.y;                 // 0/1 -> o2 in [16*oh, 16*oh+16)
    for (int i = tid; i < CIN*16; i += 128) {
        int c   = i >> 4;                 // 0..255
        int o2  = 16*oh + (i & 15);
        sW2[i] = pk2(Wc[(2*o2)*WROW + c], Wc[(2*o2+1)*WROW + c]);
    }
    __syncthreads();

    int gp = blockIdx.x * 128 + tid;      // 0 .. BATCH*PLOW-1
    int b  = gp >> 14;
    int p  = gp & (PLOW-1);
    const float* xb = x + b*CIN*PLOW + p;

    unsigned long long acc2[16];
#pragma unroll
    for (int o = 0; o < 16; o++) acc2[o] = 0ULL;

    for (int c = 0; c < CIN; c += 4) {
        unsigned long long vv0 = pk2(xb[(c+0)*PLOW], xb[(c+0)*PLOW]);
        unsigned long long vv1 = pk2(xb[(c+1)*PLOW], xb[(c+1)*PLOW]);
        unsigned long long vv2 = pk2(xb[(c+2)*PLOW], xb[(c+2)*PLOW]);
        unsigned long long vv3 = pk2(xb[(c+3)*PLOW], xb[(c+3)*PLOW]);
#pragma unroll
        for (int o2 = 0; o2 < 16; o2 += 2) {
            ulonglong2 w0 = *(const ulonglong2*)&sW2[(c+0)*16 + o2];
            fma2(acc2[o2],   w0.x, vv0);  fma2(acc2[o2+1], w0.y, vv0);
            ulonglong2 w1 = *(const ulonglong2*)&sW2[(c+1)*16 + o2];
            fma2(acc2[o2],   w1.x, vv1);  fma2(acc2[o2+1], w1.y, vv1);
            ulonglong2 w2 = *(const ulonglong2*)&sW2[(c+2)*16 + o2];
            fma2(acc2[o2],   w2.x, vv2);  fma2(acc2[o2+1], w2.y, vv2);
            ulonglong2 w3 = *(const ulonglong2*)&sW2[(c+3)*16 + o2];
            fma2(acc2[o2],   w3.x, vv3);  fma2(acc2[o2+1], w3.y, vv3);
        }
    }
    float* yl = g_ylow + b*PL*PLOW + p;
#pragma unroll
    for (int o2 = 0; o2 < 16; o2++) {
        float lo, hi;
        upk2(lo, hi, acc2[o2]);
        int o = 2*(16*oh + o2);
        yl[o*PLOW]       = lo;
        yl[(o+1)*PLOW]   = hi;
    }
}

// ---------------------------------------------------------------------------
// K2: xv[b,o,h,w] = bilerp(y_low[b,o]) + sum_{g<64} W[o,256+g]*guide[b,g,h,w]
// o-split across blockIdx.y: 32 outputs per block, acc2[16].
// ---------------------------------------------------------------------------
__global__ void __launch_bounds__(256) k_xv(const float* __restrict__ guide,
                                            const float* __restrict__ Wc) {
    __shared__ __align__(16) unsigned long long sW2[GC*16];  // 8 KB
    int tid = threadIdx.x;
    int oh  = blockIdx.y;
    for (int i = tid; i < GC*16; i += 256) {
        int g  = i >> 4;
        int o2 = 16*oh + (i & 15);
        sW2[i] = pk2(Wc[(2*o2)*WROW + CIN + g], Wc[(2*o2+1)*WROW + CIN + g]);
    }
    __syncthreads();

    int gp = blockIdx.x * 256 + tid;      // 0 .. BATCH*PFUL-1
    int b  = gp >> 16;
    int p  = gp & (PFUL-1);
    int h  = p >> 8, w = p & 255;

    // vertical taps
    int my = h >> 1; int y0, y1; float wy1;
    if (h & 1) { y0 = my; y1 = (my+1 < HL) ? my+1 : HL-1; wy1 = 0.25f; }
    else       { y1 = my; y0 = (my > 0)    ? my-1 : 0;    wy1 = 0.75f; }
    float wy0 = 1.f - wy1;
    // horizontal taps
    int mx = w >> 1; int x0, x1; float wx1;
    if (w & 1) { x0 = mx; x1 = (mx+1 < WL) ? mx+1 : WL-1; wx1 = 0.25f; }
    else       { x1 = mx; x0 = (mx > 0)    ? mx-1 : 0;    wx1 = 0.75f; }
    float wx0 = 1.f - wx1;

    int i00 = y0*WL + x0, i01 = y0*WL + x1, i10 = y1*WL + x0, i11 = y1*WL + x1;
    float w00 = wy0*wx0, w01 = wy0*wx1, w10 = wy1*wx0, w11 = wy1*wx1;

    const float* yl = g_ylow + b*PL*PLOW;
    unsigned long long acc2[16];
#pragma unroll
    for (int o2 = 0; o2 < 16; o2++) {
        const float* ya = yl + 2*(16*oh + o2)*PLOW;
        const float* yb = ya + PLOW;
        float lo = w00*ya[i00] + w01*ya[i01] + w10*ya[i10] + w11*ya[i11];
        float hi = w00*yb[i00] + w01*yb[i01] + w10*yb[i10] + w11*yb[i11];
        acc2[o2] = pk2(lo, hi);
    }

    const float* gb = guide + b*GC*PFUL + p;
    for (int g = 0; g < GC; g += 2) {
        unsigned long long vv0 = pk2(gb[(g+0)<<16], gb[(g+0)<<16]);
        unsigned long long vv1 = pk2(gb[(g+1)<<16], gb[(g+1)<<16]);
#pragma unroll
        for (int o2 = 0; o2 < 16; o2 += 2) {
            ulonglong2 w0 = *(const ulonglong2*)&sW2[(g+0)*16 + o2];
            fma2(acc2[o2],   w0.x, vv0);  fma2(acc2[o2+1], w0.y, vv0);
            ulonglong2 w1 = *(const ulonglong2*)&sW2[(g+1)*16 + o2];
            fma2(acc2[o2],   w1.x, vv1);  fma2(acc2[o2+1], w1.y, vv1);
        }
    }
    float* xvp = g_xv + b*PL*PFUL + p;
#pragma unroll
    for (int o2 = 0; o2 < 16; o2++) {
        float lo, hi;
        upk2(lo, hi, acc2[o2]);
        int o = 2*(16*oh + o2);
        xvp[o<<16]     = lo;
        xvp[(o+1)<<16] = hi;
    }
}

// ---------------------------------------------------------------------------
// K3: 3x3 local attention. v4: both phases stream 16-channel chunks through
// ONE 20.7 KB smem tile. Phase 1: guide chunks -> 9 score partials.
// Phase 2: V chunks through the SAME buffer -> output taps via LDS instead
// of 9 gmem loads per channel (~7x fewer L1tex wavefronts).
// Zero-padded tiles give reference zero-pad semantics in both phases.
// ---------------------------------------------------------------------------
#define ACH 16
#define ATILE_ELEMS (ACH*18*18)   // 5184 floats = 20736 B
__global__ void __launch_bounds__(256) k_attn(const float* __restrict__ guide,
                                              float* __restrict__ out) {
    extern __shared__ float sT[];   // shared tile buffer (guide, then V)

    int b   = blockIdx.z;
    int x0t = blockIdx.x << 4;
    int y0t = blockIdx.y << 4;
    int tid = threadIdx.x;

    int lx = tid & 15, ly = tid >> 4;
    int base = (ly + 1)*18 + (lx + 1);

    const float* gbase = guide + b*GC*PFUL;
    const float* vbase = g_xv  + b*PL*PFUL;

    float s[9];
#pragma unroll
    for (int t = 0; t < 9; t++) s[t] = 0.f;

    // ---- Phase 1: scores over guide chunks ----
    for (int ch = 0; ch < GC; ch += ACH) {
        __syncthreads();   // previous chunk fully consumed
        for (int i = tid; i < ATILE_ELEMS; i += 256) {
            int c   = i / 324;                 // local channel 0..15
            int rem = i - c*324;
            int r   = rem / 18;
            int col = rem - r*18;
            int gy = y0t + r - 1, gx = x0t + col - 1;
            float gv = 0.f;
            if ((unsigned)gy < 256u && (unsigned)gx < 256u)
                gv = gbase[((ch + c) << 16) + (gy << 8) + gx];
            sT[i] = gv;
        }
        __syncthreads();

#pragma unroll 2
        for (int c = 0; c < ACH; c++) {
            const float* gc = sT + c*324 + base;
            float q = gc[0];
            s[0] += q * gc[-19];
            s[1] += q * gc[-18];
            s[2] += q * gc[-17];
            s[3] += q * gc[-1];
            s[4] += q * q;
            s[5] += q * gc[1];
            s[6] += q * gc[17];
            s[7] += q * gc[18];
            s[8] += q * gc[19];
        }
    }

    // ---- softmax (zero-padded k already matches reference logits) ----
    float m = s[0];
#pragma unroll
    for (int t = 1; t < 9; t++) m = fmaxf(m, s[t]);
    float a[9], ssum = 0.f;
#pragma unroll
    for (int t = 0; t < 9; t++) { a[t] = expf((s[t] - m)*0.125f); ssum += a[t]; }
    float inv = 1.f / ssum;
#pragma unroll
    for (int t = 0; t < 9; t++) a[t] *= inv;

    // ---- Phase 2: output over V chunks through the same smem tile ----
    float* ob = out + b*PL*PFUL + ((y0t + ly) << 8) + (x0t + lx);
    for (int ch = 0; ch < PL; ch += ACH) {
        __syncthreads();   // previous chunk fully consumed
        for (int i = tid; i < ATILE_ELEMS; i += 256) {
            int c   = i / 324;
            int rem = i - c*324;
            int r   = rem / 18;
            int col = rem - r*18;
            int gy = y0t + r - 1, gx = x0t + col - 1;
            float vv = 0.f;
            if ((unsigned)gy < 256u && (unsigned)gx < 256u)
                vv = vbase[((ch + c) << 16) + (gy << 8) + gx];
            sT[i] = vv;
        }
        __syncthreads();

#pragma unroll 2
        for (int c = 0; c < ACH; c++) {
            const float* vc = sT + c*324 + base;
            float acc = a[0]*vc[-19] + a[1]*vc[-18] + a[2]*vc[-17]
                      + a[3]*vc[-1]  + a[4]*vc[0]   + a[5]*vc[1]
                      + a[6]*vc[17]  + a[7]*vc[18]  + a[8]*vc[19];
            ob[(ch + c) << 16] = acc;
        }
    }
}

// ---------------------------------------------------------------------------
// K0: zero BN accumulators
// ---------------------------------------------------------------------------
__global__ void k_zero() {
    int i = threadIdx.x;
    if (i < PL) { g_sum[i] = 0.0; g_sumsq[i] = 0.0; }
}

// ---------------------------------------------------------------------------
// K3b: per-channel sum / sumsq reduction over (B,H,W)
// grid (64, 32): each block reduces 8192 contiguous floats of one channel.
// ---------------------------------------------------------------------------
__global__ void __launch_bounds__(256) k_stats(const float* __restrict__ out) {
    int o = blockIdx.x, s = blockIdx.y;      // s: 0..31, 8 slices per image
    int b = s >> 3;
    const float4* p4 = (const float4*)(out + ((b*PL + o) << 16) + ((s & 7) << 13));
    float sum = 0.f, ss = 0.f;
    for (int i = threadIdx.x; i < 2048; i += 256) {
        float4 v = p4[i];
        sum += v.x + v.y + v.z + v.w;
        ss  += v.x*v.x + v.y*v.y + v.z*v.z + v.w*v.w;
    }
#pragma unroll
    for (int d = 16; d; d >>= 1) {
        sum += __shfl_xor_sync(~0u, sum, d);
        ss  += __shfl_xor_sync(~0u, ss, d);
    }
    __shared__ float wsum[8], wss[8];
    int w = threadIdx.x >> 5;
    if ((threadIdx.x & 31) == 0) { wsum[w] = sum; wss[w] = ss; }
    __syncthreads();
    if (threadIdx.x == 0) {
        float ts = 0.f, tq = 0.f;
#pragma unroll
        for (int i = 0; i < 8; i++) { ts += wsum[i]; tq += wss[i]; }
        atomicAdd(&g_sum[o],   (double)ts);
        atomicAdd(&g_sumsq[o], (double)tq);
    }
}

// ---------------------------------------------------------------------------
// K4: finalize BN scale/shift (population variance, eps=1e-5)
// ---------------------------------------------------------------------------
__global__ void k_final(const float* __restrict__ gamma,
                        const float* __restrict__ beta) {
    int o = threadIdx.x;
    if (o < PL) {
        double N    = (double)(BATCH * PFUL);
        double mean = g_sum[o] / N;
        double var  = g_sumsq[o] / N - mean*mean;
        double sc   = (double)gamma[o] / sqrt(var + 1e-5);
        g_scale[o] = (float)sc;
        g_shift[o] = (float)((double)beta[o] - mean*sc);
    }
}

// ---------------------------------------------------------------------------
// K5: apply BN in place (float4, exact grid)
// ---------------------------------------------------------------------------
__global__ void __launch_bounds__(256) k_bn(float* __restrict__ out) {
    int i = blockIdx.x * 256 + threadIdx.x;   // float4 index; 4194304 total
    int o = (i >> 14) & 63;                   // 16384 float4 per channel
    float sc = g_scale[o], sh = g_shift[o];
    float4 v = ((float4*)out)[i];
    v.x = v.x*sc + sh; v.y = v.y*sc + sh;
    v.z = v.z*sc + sh; v.w = v.w*sc + sh;
    ((float4*)out)[i] = v;
}

// ---------------------------------------------------------------------------
extern "C" void kernel_launch(void* const* d_in, const int* in_sizes, int n_in,
                              void* d_out, int out_size) {
    const float* x     = (const float*)d_in[0];
    const float* guide = (const float*)d_in[1];
    const float* Wc    = (const float*)d_in[2];
    const float* gamma = (const float*)d_in[3];
    const float* beta  = (const float*)d_in[4];
    float* out = (float*)d_out;

    const int conv_smem = CIN*16*(int)sizeof(unsigned long long);   // 32768 B
    const int attn_smem = ATILE_ELEMS * (int)sizeof(float);         // 20736 B
    cudaFuncSetAttribute(k_conv_low, cudaFuncAttributeMaxDynamicSharedMemorySize, conv_smem);
    cudaFuncSetAttribute(k_attn,     cudaFuncAttributeMaxDynamicSharedMemorySize, attn_smem);

    k_conv_low<<<dim3((BATCH*PLOW)/128, 2), 128, conv_smem>>>(x, Wc);
    k_xv<<<dim3((BATCH*PFUL)/256, 2), 256>>>(guide, Wc);
    k_zero<<<1, 64>>>();
    k_attn<<<dim3(WW/16, HH/16, BATCH), 256, attn_smem>>>(guide, out);
    k_stats<<<dim3(PL, 32), 256>>>(out);
    k_final<<<1, 64>>>(gamma, beta);
    k_bn<<<(BATCH*PL*PFUL)/4/256, 256>>>(out);
}